// round 9
// baseline (speedup 1.0000x reference)
#include <cuda_runtime.h>

#define ZDIM 8
#define EDIM 32
#define HDIM 64
#define NEG 0.01f
#define LEN 510
#define NTOT 32640            /* 64 * 510 = 255 * 128 */
#define LOG_OFF (NTOT*ZDIM)
#define CTA 128
#define SA 68                 /* shA row stride (floats) */
#define SB 72                 /* W2 row stride (floats) */

/* dynamic smem layout (float offsets) */
#define OFF_A    0                       /* 128*SA = 8704 */
#define OFF_W2H  (OFF_A   + 128*SA)      /* 64*SB = 4608  */
#define OFF_W2L  (OFF_W2H + 64*SB)
#define OFF_W1   (OFF_W2L + 64*SB)       /* 33*64 = 2112  */
#define OFF_B1   (OFF_W1  + 33*64)
#define OFF_B2   (OFF_B1  + 64)
#define OFF_W3   (OFF_B2  + 64)
#define OFF_W3N  (OFF_W3  + 64)
#define OFF_CWH  (OFF_W3N + 64)          /* tf32 hi/lo of cw  = W1[32][i]        */
#define OFF_CWL  (OFF_CWH + 64)
#define OFF_CWNH (OFF_CWL + 64)          /* tf32 hi/lo of 0.01*cw (leaky' branch) */
#define OFF_CWNL (OFF_CWNH + 64)
#define OFF_B3   (OFF_CWNL + 64)
#define SMEM_FLOATS (OFF_B3 + 4)
#define SMEM_BYTES  (SMEM_FLOATS * 4)    /* ~82.2 KB -> 2 CTAs/SM */

__device__ float g_dlog[ZDIM * NTOT];

__device__ __forceinline__ unsigned f2tf(float a){
    unsigned u; asm("cvt.rna.tf32.f32 %0, %1;" : "=r"(u) : "f"(a)); return u;
}
__device__ __forceinline__ void mma8(float* c, const unsigned* a, unsigned b0, unsigned b1){
    asm volatile("mma.sync.aligned.m16n8k8.row.col.f32.tf32.tf32.f32 "
                 "{%0,%1,%2,%3}, {%4,%5,%6,%7}, {%8,%9}, {%0,%1,%2,%3};"
                 : "+f"(c[0]), "+f"(c[1]), "+f"(c[2]), "+f"(c[3])
                 : "r"(a[0]), "r"(a[1]), "r"(a[2]), "r"(a[3]), "r"(b0), "r"(b1));
}
__device__ __forceinline__ float leaky(float p){
    return fmaxf(p, 0.f) + NEG * fminf(p, 0.f);
}

__global__ __launch_bounds__(CTA, 2)
void mlp_jvp_tc(const float* __restrict__ x,
                const float* __restrict__ emb,
                const float* __restrict__ W1,
                const float* __restrict__ b1,
                const float* __restrict__ W2,
                const float* __restrict__ b2,
                const float* __restrict__ W3,
                const float* __restrict__ b3,
                float* __restrict__ out)
{
    extern __shared__ float sm[];
    unsigned* smu = reinterpret_cast<unsigned*>(sm);
    const int tid = threadIdx.x;
    const int z   = blockIdx.y;

    /* ---- stage weights; W2, cw, 0.01*cw pre-split to tf32 hi/lo ---- */
    {
        const float* g1 = W1 + z*33*HDIM;
        for (int i = tid; i < 33*HDIM; i += CTA) sm[OFF_W1 + i] = g1[i];
        const float* g2 = W2 + z*HDIM*HDIM;
        for (int i = tid; i < HDIM*HDIM; i += CTA){
            float w  = g2[i];
            unsigned uh = f2tf(w);
            float hi = __uint_as_float(uh);
            float lo = __uint_as_float(f2tf(w - hi));
            int r = i >> 6, c = i & 63;
            sm[OFF_W2H + r*SB + c] = hi;
            sm[OFF_W2L + r*SB + c] = lo;
        }
        if (tid < HDIM){
            sm[OFF_B1 + tid]  = b1[z*HDIM + tid];
            sm[OFF_B2 + tid]  = b2[z*HDIM + tid];
            float w3v = W3[z*HDIM + tid];
            sm[OFF_W3  + tid] = w3v;
            sm[OFF_W3N + tid] = NEG * w3v;
            float cwv = g1[32*HDIM + tid];
            unsigned uh = f2tf(cwv);
            smu[OFF_CWH + tid] = uh;
            smu[OFF_CWL + tid] = f2tf(cwv - __uint_as_float(uh));
            float cwn = NEG * cwv;                 /* leaky' negative-branch slope */
            unsigned un = f2tf(cwn);
            smu[OFF_CWNH + tid] = un;
            smu[OFF_CWNL + tid] = f2tf(cwn - __uint_as_float(un));
        }
        if (tid == 0) sm[OFF_B3] = b3[z];
    }
    __syncthreads();

    /* ---- phase 1: scalar layer 1 for row = tid; h -> smem ---- */
    {
        const int n   = blockIdx.x * CTA + tid;
        const int bb  = n / LEN;
        const int tt  = n - bb * LEN;
        const int src = bb * 512 + tt + 2;
        const float4* e4 = reinterpret_cast<const float4*>(emb + (size_t)src * EDIM);
        const float xt = x[src * ZDIM + z];

        float acc[HDIM];
        #pragma unroll
        for (int h = 0; h < HDIM; h++) acc[h] = sm[OFF_B1 + h];

        #pragma unroll 1
        for (int g = 0; g < 8; g++){
            float4 v = __ldg(e4 + g);
            const float* w0 = sm + OFF_W1 + (4*g+0)*HDIM;
            const float* w1r= sm + OFF_W1 + (4*g+1)*HDIM;
            const float* w2r= sm + OFF_W1 + (4*g+2)*HDIM;
            const float* w3r= sm + OFF_W1 + (4*g+3)*HDIM;
            #pragma unroll
            for (int h = 0; h < HDIM; h++){
                float a = acc[h];
                a = fmaf(v.x, w0[h],  a);
                a = fmaf(v.y, w1r[h], a);
                a = fmaf(v.z, w2r[h], a);
                a = fmaf(v.w, w3r[h], a);
                acc[h] = a;
            }
        }
        const float* wx = sm + OFF_W1 + 32*HDIM;
        #pragma unroll
        for (int h = 0; h < HDIM; h++) acc[h] = fmaf(xt, wx[h], acc[h]);

        float* arow = sm + OFF_A + tid*SA;
        #pragma unroll
        for (int q = 0; q < HDIM/4; q++){
            float4 hv;
            hv.x = leaky(acc[4*q+0]); hv.y = leaky(acc[4*q+1]);
            hv.z = leaky(acc[4*q+2]); hv.w = leaky(acc[4*q+3]);
            *reinterpret_cast<float4*>(arow + 4*q) = hv;
        }
    }
    __syncthreads();

    /* ---- phase 2: tensor-core layer 2 (+fused layer 3) ---- */
    const int wid  = tid >> 5;
    const int lane = tid & 31;
    const int g    = lane >> 2;
    const int c    = lane & 3;
    const int rowbase = wid * 32;

    float C[2][8][4];
    #pragma unroll
    for (int nf = 0; nf < 8; nf++){
        float bj0 = sm[OFF_B2 + nf*8 + 2*c];
        float bj1 = sm[OFF_B2 + nf*8 + 2*c + 1];
        #pragma unroll
        for (int mf = 0; mf < 2; mf++){
            C[mf][nf][0] = bj0; C[mf][nf][1] = bj1;
            C[mf][nf][2] = bj0; C[mf][nf][3] = bj1;
        }
    }

    /* forward GEMM: 3xTF32 split */
    #pragma unroll 1
    for (int kb = 0; kb < 8; kb++){
        const int k0 = kb*8 + c, k1 = k0 + 4;
        unsigned Ah[2][4], Al[2][4];
        #pragma unroll
        for (int mf = 0; mf < 2; mf++){
            const float* ar0 = sm + OFF_A + (rowbase + mf*16 + g)*SA;
            const float* ar1 = ar0 + 8*SA;
            float a0 = ar0[k0], a1 = ar1[k0], a2 = ar0[k1], a3 = ar1[k1];
            Ah[mf][0] = f2tf(a0); Ah[mf][1] = f2tf(a1);
            Ah[mf][2] = f2tf(a2); Ah[mf][3] = f2tf(a3);
            Al[mf][0] = f2tf(a0 - __uint_as_float(Ah[mf][0]));
            Al[mf][1] = f2tf(a1 - __uint_as_float(Ah[mf][1]));
            Al[mf][2] = f2tf(a2 - __uint_as_float(Ah[mf][2]));
            Al[mf][3] = f2tf(a3 - __uint_as_float(Ah[mf][3]));
        }
        #pragma unroll
        for (int nf = 0; nf < 8; nf++){
            const int bcol = nf*8 + g;
            unsigned bh0 = __float_as_uint(sm[OFF_W2H + (kb*8+c  )*SB + bcol]);
            unsigned bh1 = __float_as_uint(sm[OFF_W2H + (kb*8+c+4)*SB + bcol]);
            unsigned bl0 = __float_as_uint(sm[OFF_W2L + (kb*8+c  )*SB + bcol]);
            unsigned bl1 = __float_as_uint(sm[OFF_W2L + (kb*8+c+4)*SB + bcol]);
            #pragma unroll
            for (int mf = 0; mf < 2; mf++){
                mma8(C[mf][nf], Ah[mf], bh0, bh1);
                mma8(C[mf][nf], Al[mf], bh0, bh1);
                mma8(C[mf][nf], Ah[mf], bl0, bl1);
            }
        }
    }

    /* fwd epilogue: leaky -> W3 dot partials; keep sign mask for tangent */
    float opart[4] = {0.f, 0.f, 0.f, 0.f};
    unsigned mask[4] = {0u, 0u, 0u, 0u};
    #pragma unroll
    for (int mf = 0; mf < 2; mf++)
    #pragma unroll
    for (int nf = 0; nf < 8; nf++)
    #pragma unroll
    for (int e = 0; e < 4; e++){
        float v = C[mf][nf][e];
        int rs = mf*2 + (e>>1);
        int j  = nf*8 + 2*c + (e&1);
        unsigned s = (v >= 0.f);
        mask[rs] |= s << (nf*2 + (e&1));
        float h2 = s ? v : NEG * v;
        opart[rs] = fmaf(h2, sm[OFF_W3 + j], opart[rs]);
    }

    /* tangent GEMM: 3xTF32; dh selects exact split of cw or 0.01*cw by sign(h) */
    #pragma unroll
    for (int mf = 0; mf < 2; mf++)
    #pragma unroll
    for (int nf = 0; nf < 8; nf++)
    #pragma unroll
    for (int e = 0; e < 4; e++) C[mf][nf][e] = 0.f;

    #pragma unroll 1
    for (int kb = 0; kb < 8; kb++){
        const int k0 = kb*8 + c, k1 = k0 + 4;
        const unsigned ph0 = smu[OFF_CWH + k0],  pl0 = smu[OFF_CWL + k0];
        const unsigned nh0 = smu[OFF_CWNH + k0], nl0 = smu[OFF_CWNL + k0];
        const unsigned ph1 = smu[OFF_CWH + k1],  pl1 = smu[OFF_CWL + k1];
        const unsigned nh1 = smu[OFF_CWNH + k1], nl1 = smu[OFF_CWNL + k1];
        unsigned Ah[2][4], Al[2][4];
        #pragma unroll
        for (int mf = 0; mf < 2; mf++){
            const float* ar0 = sm + OFF_A + (rowbase + mf*16 + g)*SA;
            const float* ar1 = ar0 + 8*SA;
            bool p0 = (ar0[k0] >= 0.f);           /* sign(h)==sign(pre1) */
            bool p1 = (ar1[k0] >= 0.f);
            bool p2 = (ar0[k1] >= 0.f);
            bool p3 = (ar1[k1] >= 0.f);
            Ah[mf][0] = p0 ? ph0 : nh0;  Al[mf][0] = p0 ? pl0 : nl0;
            Ah[mf][1] = p1 ? ph0 : nh0;  Al[mf][1] = p1 ? pl0 : nl0;
            Ah[mf][2] = p2 ? ph1 : nh1;  Al[mf][2] = p2 ? pl1 : nl1;
            Ah[mf][3] = p3 ? ph1 : nh1;  Al[mf][3] = p3 ? pl1 : nl1;
        }
        #pragma unroll
        for (int nf = 0; nf < 8; nf++){
            const int bcol = nf*8 + g;
            unsigned bh0 = __float_as_uint(sm[OFF_W2H + (kb*8+c  )*SB + bcol]);
            unsigned bh1 = __float_as_uint(sm[OFF_W2H + (kb*8+c+4)*SB + bcol]);
            unsigned bl0 = __float_as_uint(sm[OFF_W2L + (kb*8+c  )*SB + bcol]);
            unsigned bl1 = __float_as_uint(sm[OFF_W2L + (kb*8+c+4)*SB + bcol]);
            #pragma unroll
            for (int mf = 0; mf < 2; mf++){
                mma8(C[mf][nf], Ah[mf], bh0, bh1);
                mma8(C[mf][nf], Al[mf], bh0, bh1);
                mma8(C[mf][nf], Ah[mf], bl0, bl1);
            }
        }
    }

    /* tangent epilogue: dacc partials via saved sign mask */
    float dpart[4] = {0.f, 0.f, 0.f, 0.f};
    #pragma unroll
    for (int mf = 0; mf < 2; mf++)
    #pragma unroll
    for (int nf = 0; nf < 8; nf++)
    #pragma unroll
    for (int e = 0; e < 4; e++){
        float t = C[mf][nf][e];
        int rs = mf*2 + (e>>1);
        int j  = nf*8 + 2*c + (e&1);
        float w = (mask[rs] >> (nf*2 + (e&1))) & 1u ? sm[OFF_W3 + j] : sm[OFF_W3N + j];
        dpart[rs] = fmaf(w, t, dpart[rs]);
    }

    /* quad reduction (over c) and writeback */
    const float b3v = sm[OFF_B3];
    #pragma unroll
    for (int rs = 0; rs < 4; rs++){
        float v = opart[rs];
        v += __shfl_xor_sync(0xffffffffu, v, 1);
        v += __shfl_xor_sync(0xffffffffu, v, 2);
        float d = dpart[rs];
        d += __shfl_xor_sync(0xffffffffu, d, 1);
        d += __shfl_xor_sync(0xffffffffu, d, 2);
        if (c == 0){
            int row  = rowbase + (rs>>1)*16 + (rs&1)*8 + g;
            int nrow = blockIdx.x * CTA + row;
            out[(size_t)nrow * ZDIM + z] = v + b3v;
            g_dlog[z*NTOT + nrow] = __logf(fabsf(d));
        }
    }
}

__global__ void logdet_reduce4(float* __restrict__ out){
    int t = blockIdx.x * blockDim.x + threadIdx.x;
    if (t >= NTOT/4) return;
    int base = t * 4;
    float4 s = make_float4(0.f, 0.f, 0.f, 0.f);
    #pragma unroll
    for (int zz = 0; zz < ZDIM; zz++){
        float4 v = *reinterpret_cast<const float4*>(&g_dlog[zz*NTOT + base]);
        s.x += v.x; s.y += v.y; s.z += v.z; s.w += v.w;
    }
    *reinterpret_cast<float4*>(&out[LOG_OFF + base]) = s;
}

extern "C" void kernel_launch(void* const* d_in, const int* in_sizes, int n_in,
                              void* d_out, int out_size){
    const float* x    = (const float*)d_in[0];
    const float* embv = (const float*)d_in[1];
    const float* W1   = (const float*)d_in[2];
    const float* b1   = (const float*)d_in[3];
    const float* W2   = (const float*)d_in[4];
    const float* b2   = (const float*)d_in[5];
    const float* W3   = (const float*)d_in[6];
    const float* b3   = (const float*)d_in[7];
    float* out = (float*)d_out;

    cudaFuncSetAttribute(mlp_jvp_tc, cudaFuncAttributeMaxDynamicSharedMemorySize, SMEM_BYTES);
    dim3 grid(NTOT / CTA, ZDIM);
    mlp_jvp_tc<<<grid, CTA, SMEM_BYTES>>>(x, embv, W1, b1, W2, b2, W3, b3, out);
    logdet_reduce4<<<(NTOT/4 + 255)/256, 256>>>(out);
}

// round 10
// speedup vs baseline: 1.1006x; 1.1006x over previous
#include <cuda_runtime.h>

#define ZDIM 8
#define HDIM 64
#define NEG 0.01f
#define LEN 510
#define NTOT 32640            /* 64 * 510 = 255 * 128 */
#define LOG_OFF (NTOT*ZDIM)
#define CTA 128

#define SE 44                 /* emb tile stride (conflict-free, 16B-aligned rows) */
#define SA 66                 /* h tile stride (8B-aligned float2 stores) */
#define S1 65                 /* W1 split stride */
#define S2 65                 /* W2 split stride */
#define K1 40                 /* layer-1 K padded: 32 emb + xt + 7 zeros */

/* dynamic smem layout (float offsets) */
#define OFF_E    0                        /* 128*SE = 5632 */
#define OFF_A    (OFF_E + 128*SE)         /* 128*SA = 8448 */
#define OFF_W1H  (OFF_A + 128*SA)         /* K1*S1 = 2600 */
#define OFF_W1L  (OFF_W1H + K1*S1)
#define OFF_W2H  (OFF_W1L + K1*S1)        /* 64*S2 = 4160 */
#define OFF_W2L  (OFF_W2H + 64*S2)
#define OFF_B1   (OFF_W2L + 64*S2)
#define OFF_B2   (OFF_B1 + 64)
#define OFF_W3   (OFF_B2 + 64)
#define OFF_W3N  (OFF_W3 + 64)
#define OFF_CWH  (OFF_W3N + 64)           /* exact tf32 hi/lo of cw and 0.01*cw */
#define OFF_CWL  (OFF_CWH + 64)
#define OFF_CWNH (OFF_CWL + 64)
#define OFF_CWNL (OFF_CWNH + 64)
#define OFF_B3   (OFF_CWNL + 64)
#define SMEM_FLOATS (OFF_B3 + 4)
#define SMEM_BYTES  (SMEM_FLOATS * 4)     /* ~110 KB -> 2 CTAs/SM */

__device__ float g_dlog[ZDIM * NTOT];

__device__ __forceinline__ unsigned f2tf(float a){
    unsigned u; asm("cvt.rna.tf32.f32 %0, %1;" : "=r"(u) : "f"(a)); return u;
}
__device__ __forceinline__ void mma8(float* c, const unsigned* a, unsigned b0, unsigned b1){
    asm volatile("mma.sync.aligned.m16n8k8.row.col.f32.tf32.tf32.f32 "
                 "{%0,%1,%2,%3}, {%4,%5,%6,%7}, {%8,%9}, {%0,%1,%2,%3};"
                 : "+f"(c[0]), "+f"(c[1]), "+f"(c[2]), "+f"(c[3])
                 : "r"(a[0]), "r"(a[1]), "r"(a[2]), "r"(a[3]), "r"(b0), "r"(b1));
}
__device__ __forceinline__ float leaky(float p){
    return fmaxf(p, 0.f) + NEG * fminf(p, 0.f);
}

__global__ __launch_bounds__(CTA, 2)
void mlp_jvp_tc(const float* __restrict__ x,
                const float* __restrict__ emb,
                const float* __restrict__ W1,
                const float* __restrict__ b1,
                const float* __restrict__ W2,
                const float* __restrict__ b2,
                const float* __restrict__ W3,
                const float* __restrict__ b3,
                float* __restrict__ out)
{
    extern __shared__ float sm[];
    unsigned* smu = reinterpret_cast<unsigned*>(sm);
    const int tid = threadIdx.x;
    const int z   = blockIdx.y;

    /* ---- stage: W1/W2 tf32 hi/lo splits, emb+xt tile, biases, cw splits ---- */
    {
        const float* g1 = W1 + z*33*HDIM;
        for (int i = tid; i < K1*HDIM; i += CTA){
            int k = i >> 6, hcol = i & 63;
            float w = (k < 33) ? g1[k*HDIM + hcol] : 0.f;
            unsigned uh = f2tf(w);
            float hi = __uint_as_float(uh);
            float lo = __uint_as_float(f2tf(w - hi));
            sm[OFF_W1H + k*S1 + hcol] = hi;
            sm[OFF_W1L + k*S1 + hcol] = lo;
        }
        const float* g2 = W2 + z*HDIM*HDIM;
        for (int i = tid; i < HDIM*HDIM; i += CTA){
            float w  = g2[i];
            unsigned uh = f2tf(w);
            float hi = __uint_as_float(uh);
            float lo = __uint_as_float(f2tf(w - hi));
            int r = i >> 6, c = i & 63;
            sm[OFF_W2H + r*S2 + c] = hi;
            sm[OFF_W2L + r*S2 + c] = lo;
        }
        if (tid < HDIM){
            sm[OFF_B1 + tid] = b1[z*HDIM + tid];
            sm[OFF_B2 + tid] = b2[z*HDIM + tid];
            float w3v = W3[z*HDIM + tid];
            sm[OFF_W3  + tid] = w3v;
            sm[OFF_W3N + tid] = NEG * w3v;
            float cwv = g1[32*HDIM + tid];
            unsigned uh = f2tf(cwv);
            smu[OFF_CWH + tid] = uh;
            smu[OFF_CWL + tid] = f2tf(cwv - __uint_as_float(uh));
            float cwn = NEG * cwv;
            unsigned un = f2tf(cwn);
            smu[OFF_CWNH + tid] = un;
            smu[OFF_CWNL + tid] = f2tf(cwn - __uint_as_float(un));
        }
        if (tid == 0) sm[OFF_B3] = b3[z];

        /* emb+xt tile: row = tid */
        const int n   = blockIdx.x * CTA + tid;
        const int bb  = n / LEN;
        const int tt  = n - bb * LEN;
        const int src = bb * 512 + tt + 2;           /* LL=512, LAGS=2 */
        const float4* e4 = reinterpret_cast<const float4*>(emb + (size_t)src * 32);
        float* erow = sm + OFF_E + tid*SE;
        #pragma unroll
        for (int q = 0; q < 8; q++)
            *reinterpret_cast<float4*>(erow + 4*q) = __ldg(e4 + q);
        erow[32] = x[src * ZDIM + z];
        #pragma unroll
        for (int q = 33; q < K1; q++) erow[q] = 0.f;
    }
    __syncthreads();

    const int wid  = tid >> 5;
    const int lane = tid & 31;
    const int g    = lane >> 2;
    const int c    = lane & 3;
    const int rowbase = wid * 32;

    /* ---- layer 1: [128 x 40] @ [40 x 64], 3xTF32 ---- */
    {
        float C1[2][8][4];
        #pragma unroll
        for (int nf = 0; nf < 8; nf++){
            float bj0 = sm[OFF_B1 + nf*8 + 2*c];
            float bj1 = sm[OFF_B1 + nf*8 + 2*c + 1];
            #pragma unroll
            for (int mf = 0; mf < 2; mf++){
                C1[mf][nf][0] = bj0; C1[mf][nf][1] = bj1;
                C1[mf][nf][2] = bj0; C1[mf][nf][3] = bj1;
            }
        }
        #pragma unroll 1
        for (int kb = 0; kb < K1/8; kb++){
            const int k0 = kb*8 + c, k1 = k0 + 4;
            unsigned Ah[2][4], Al[2][4];
            #pragma unroll
            for (int mf = 0; mf < 2; mf++){
                const float* ar0 = sm + OFF_E + (rowbase + mf*16 + g)*SE;
                const float* ar1 = ar0 + 8*SE;
                float a0 = ar0[k0], a1 = ar1[k0], a2 = ar0[k1], a3 = ar1[k1];
                Ah[mf][0] = f2tf(a0); Ah[mf][1] = f2tf(a1);
                Ah[mf][2] = f2tf(a2); Ah[mf][3] = f2tf(a3);
                Al[mf][0] = f2tf(a0 - __uint_as_float(Ah[mf][0]));
                Al[mf][1] = f2tf(a1 - __uint_as_float(Ah[mf][1]));
                Al[mf][2] = f2tf(a2 - __uint_as_float(Ah[mf][2]));
                Al[mf][3] = f2tf(a3 - __uint_as_float(Ah[mf][3]));
            }
            #pragma unroll
            for (int nf = 0; nf < 8; nf++){
                const int bcol = nf*8 + g;
                unsigned bh0 = __float_as_uint(sm[OFF_W1H + (kb*8+c  )*S1 + bcol]);
                unsigned bh1 = __float_as_uint(sm[OFF_W1H + (kb*8+c+4)*S1 + bcol]);
                unsigned bl0 = __float_as_uint(sm[OFF_W1L + (kb*8+c  )*S1 + bcol]);
                unsigned bl1 = __float_as_uint(sm[OFF_W1L + (kb*8+c+4)*S1 + bcol]);
                #pragma unroll
                for (int mf = 0; mf < 2; mf++){
                    mma8(C1[mf][nf], Ah[mf], bh0, bh1);
                    mma8(C1[mf][nf], Al[mf], bh0, bh1);
                    mma8(C1[mf][nf], Ah[mf], bl0, bl1);
                }
            }
        }
        /* epilogue: leaky -> h tile (STS.64 pairs) */
        #pragma unroll
        for (int mf = 0; mf < 2; mf++){
            const int r0 = rowbase + mf*16 + g;
            #pragma unroll
            for (int nf = 0; nf < 8; nf++){
                float2 h01, h23;
                h01.x = leaky(C1[mf][nf][0]); h01.y = leaky(C1[mf][nf][1]);
                h23.x = leaky(C1[mf][nf][2]); h23.y = leaky(C1[mf][nf][3]);
                *reinterpret_cast<float2*>(sm + OFF_A + r0*SA      + nf*8 + 2*c) = h01;
                *reinterpret_cast<float2*>(sm + OFF_A + (r0+8)*SA  + nf*8 + 2*c) = h23;
            }
        }
    }
    __syncthreads();

    /* ---- layer 2 fused fwd+tangent (+layer 3) ---- */
    float Cf[2][8][4], Ct[2][8][4];
    #pragma unroll
    for (int nf = 0; nf < 8; nf++){
        float bj0 = sm[OFF_B2 + nf*8 + 2*c];
        float bj1 = sm[OFF_B2 + nf*8 + 2*c + 1];
        #pragma unroll
        for (int mf = 0; mf < 2; mf++){
            Cf[mf][nf][0] = bj0; Cf[mf][nf][1] = bj1;
            Cf[mf][nf][2] = bj0; Cf[mf][nf][3] = bj1;
            Ct[mf][nf][0] = 0.f; Ct[mf][nf][1] = 0.f;
            Ct[mf][nf][2] = 0.f; Ct[mf][nf][3] = 0.f;
        }
    }

    #pragma unroll 1
    for (int kb = 0; kb < 8; kb++){
        const int k0 = kb*8 + c, k1 = k0 + 4;
        const unsigned ph0 = smu[OFF_CWH + k0],  pl0 = smu[OFF_CWL + k0];
        const unsigned nh0 = smu[OFF_CWNH + k0], nl0 = smu[OFF_CWNL + k0];
        const unsigned ph1 = smu[OFF_CWH + k1],  pl1 = smu[OFF_CWL + k1];
        const unsigned nh1 = smu[OFF_CWNH + k1], nl1 = smu[OFF_CWNL + k1];
        unsigned Ah[2][4], Al[2][4], Th[2][4], Tl[2][4];
        #pragma unroll
        for (int mf = 0; mf < 2; mf++){
            const float* ar0 = sm + OFF_A + (rowbase + mf*16 + g)*SA;
            const float* ar1 = ar0 + 8*SA;
            float a0 = ar0[k0], a1 = ar1[k0], a2 = ar0[k1], a3 = ar1[k1];
            Ah[mf][0] = f2tf(a0); Ah[mf][1] = f2tf(a1);
            Ah[mf][2] = f2tf(a2); Ah[mf][3] = f2tf(a3);
            Al[mf][0] = f2tf(a0 - __uint_as_float(Ah[mf][0]));
            Al[mf][1] = f2tf(a1 - __uint_as_float(Ah[mf][1]));
            Al[mf][2] = f2tf(a2 - __uint_as_float(Ah[mf][2]));
            Al[mf][3] = f2tf(a3 - __uint_as_float(Ah[mf][3]));
            bool p0 = (a0 >= 0.f), p1 = (a1 >= 0.f), p2 = (a2 >= 0.f), p3 = (a3 >= 0.f);
            Th[mf][0] = p0 ? ph0 : nh0;  Tl[mf][0] = p0 ? pl0 : nl0;  /* dh = cw or 0.01*cw */
            Th[mf][1] = p1 ? ph0 : nh0;  Tl[mf][1] = p1 ? pl0 : nl0;
            Th[mf][2] = p2 ? ph1 : nh1;  Tl[mf][2] = p2 ? pl1 : nl1;
            Th[mf][3] = p3 ? ph1 : nh1;  Tl[mf][3] = p3 ? pl1 : nl1;
        }
        #pragma unroll
        for (int nf = 0; nf < 8; nf++){
            const int bcol = nf*8 + g;
            unsigned bh0 = __float_as_uint(sm[OFF_W2H + (kb*8+c  )*S2 + bcol]);
            unsigned bh1 = __float_as_uint(sm[OFF_W2H + (kb*8+c+4)*S2 + bcol]);
            unsigned bl0 = __float_as_uint(sm[OFF_W2L + (kb*8+c  )*S2 + bcol]);
            unsigned bl1 = __float_as_uint(sm[OFF_W2L + (kb*8+c+4)*S2 + bcol]);
            #pragma unroll
            for (int mf = 0; mf < 2; mf++){
                mma8(Cf[mf][nf], Ah[mf], bh0, bh1);   /* B loaded once, feeds 6 mma */
                mma8(Cf[mf][nf], Al[mf], bh0, bh1);
                mma8(Cf[mf][nf], Ah[mf], bl0, bl1);
                mma8(Ct[mf][nf], Th[mf], bh0, bh1);
                mma8(Ct[mf][nf], Tl[mf], bh0, bh1);
                mma8(Ct[mf][nf], Th[mf], bl0, bl1);
            }
        }
    }

    /* fused epilogue: leaky(pre2), layer-3 dots for fwd+tangent */
    float opart[4] = {0.f, 0.f, 0.f, 0.f};
    float dpart[4] = {0.f, 0.f, 0.f, 0.f};
    #pragma unroll
    for (int mf = 0; mf < 2; mf++)
    #pragma unroll
    for (int nf = 0; nf < 8; nf++)
    #pragma unroll
    for (int e = 0; e < 4; e++){
        float v = Cf[mf][nf][e];
        float t = Ct[mf][nf][e];
        int rs = mf*2 + (e>>1);
        int j  = nf*8 + 2*c + (e&1);
        bool s = (v >= 0.f);
        float h2 = s ? v : NEG * v;
        opart[rs] = fmaf(h2, sm[OFF_W3 + j], opart[rs]);
        float w = s ? sm[OFF_W3 + j] : sm[OFF_W3N + j];
        dpart[rs] = fmaf(w, t, dpart[rs]);
    }

    /* quad reduction and writeback */
    const float b3v = sm[OFF_B3];
    #pragma unroll
    for (int rs = 0; rs < 4; rs++){
        float v = opart[rs];
        v += __shfl_xor_sync(0xffffffffu, v, 1);
        v += __shfl_xor_sync(0xffffffffu, v, 2);
        float d = dpart[rs];
        d += __shfl_xor_sync(0xffffffffu, d, 1);
        d += __shfl_xor_sync(0xffffffffu, d, 2);
        if (c == 0){
            int row  = rowbase + (rs>>1)*16 + (rs&1)*8 + g;
            int nrow = blockIdx.x * CTA + row;
            out[(size_t)nrow * ZDIM + z] = v + b3v;
            g_dlog[z*NTOT + nrow] = __logf(fabsf(d));
        }
    }
}

__global__ void logdet_reduce4(float* __restrict__ out){
    int t = blockIdx.x * blockDim.x + threadIdx.x;
    if (t >= NTOT/4) return;
    int base = t * 4;
    float4 s = make_float4(0.f, 0.f, 0.f, 0.f);
    #pragma unroll
    for (int zz = 0; zz < ZDIM; zz++){
        float4 v = *reinterpret_cast<const float4*>(&g_dlog[zz*NTOT + base]);
        s.x += v.x; s.y += v.y; s.z += v.z; s.w += v.w;
    }
    *reinterpret_cast<float4*>(&out[LOG_OFF + base]) = s;
}

extern "C" void kernel_launch(void* const* d_in, const int* in_sizes, int n_in,
                              void* d_out, int out_size){
    const float* x    = (const float*)d_in[0];
    const float* embv = (const float*)d_in[1];
    const float* W1   = (const float*)d_in[2];
    const float* b1   = (const float*)d_in[3];
    const float* W2   = (const float*)d_in[4];
    const float* b2   = (const float*)d_in[5];
    const float* W3   = (const float*)d_in[6];
    const float* b3   = (const float*)d_in[7];
    float* out = (float*)d_out;

    cudaFuncSetAttribute(mlp_jvp_tc, cudaFuncAttributeMaxDynamicSharedMemorySize, SMEM_BYTES);
    dim3 grid(NTOT / CTA, ZDIM);
    mlp_jvp_tc<<<grid, CTA, SMEM_BYTES>>>(x, embv, W1, b1, W2, b2, W3, b3, out);
    logdet_reduce4<<<(NTOT/4 + 255)/256, 256>>>(out);
}

// round 12
// speedup vs baseline: 1.7520x; 1.5918x over previous
#include <cuda_runtime.h>
#include <cuda_fp16.h>
#include <cstdint>

#define ZDIM 8
#define HDIM 64
#define NEG 0.01f
#define LEN 510
#define NTOT 32640            /* 64 * 510 = 255 * 128 */
#define LOG_OFF (NTOT*ZDIM)
#define CTA 128
#define K1 48                 /* layer-1 K: 32 emb + xt + 15 zeros (3 x k16) */

/* ---- smem byte offsets ---- */
/* phase-1 region (aliased with phase-2 A/T tiles):                       */
#define R_EH   0              /* E  hi [128][56]h = 14336                  */
#define R_EL   14336          /* E  lo                                     */
#define R_B1H  28672          /* W1^T hi [64][56]h = 7168                  */
#define R_B1L  35840
/* phase-2 tiles (overwrite phase-1 after barrier):                        */
#define R_A2H  0              /* h  hi [128][72]h = 18432                  */
#define R_A2L  18432
#define R_TH   36864          /* tangent hi [128][72]h                     */
#define R_TL   55296
/* persistent:                                                             */
#define R_W2H  73728          /* W2^T hi [64][72]h = 9216                  */
#define R_W2L  82944
#define MISC   92160
#define M_B1   (MISC+0)       /* float[64]  */
#define M_B2   (MISC+256)
#define M_W3   (MISC+512)
#define M_W3N  (MISC+768)
#define M_CWH  (MISC+1024)    /* __half[64] splits of cw / 0.01*cw */
#define M_CWL  (MISC+1152)
#define M_CWNH (MISC+1280)
#define M_CWNL (MISC+1408)
#define M_B3   (MISC+1536)
#define SMEM_BYTES (MISC+1600)   /* 93760 B -> 2 CTAs/SM */

#define SE1 112               /* layer-1 tile row stride, bytes */
#define S2  144               /* layer-2 tile row stride, bytes */

__device__ float g_dlog[ZDIM * NTOT];

__device__ __forceinline__ void mma16(float* c, const uint32_t* a, uint32_t b0, uint32_t b1){
    asm volatile("mma.sync.aligned.m16n8k16.row.col.f32.f16.f16.f32 "
                 "{%0,%1,%2,%3}, {%4,%5,%6,%7}, {%8,%9}, {%0,%1,%2,%3};"
                 : "+f"(c[0]), "+f"(c[1]), "+f"(c[2]), "+f"(c[3])
                 : "r"(a[0]), "r"(a[1]), "r"(a[2]), "r"(a[3]), "r"(b0), "r"(b1));
}
__device__ __forceinline__ float leaky(float p){
    return fmaxf(p, 0.f) + NEG * fminf(p, 0.f);
}
/* split 8 floats into fp16 hi/lo uint4 blocks */
__device__ __forceinline__ void pack8(const float* v, uint4& hi, uint4& lo){
    __half2* hp = reinterpret_cast<__half2*>(&hi);
    __half2* lp = reinterpret_cast<__half2*>(&lo);
    #pragma unroll
    for (int p = 0; p < 4; p++){
        float a = v[2*p], b = v[2*p+1];
        __half ah = __float2half_rn(a), bh = __float2half_rn(b);
        __half al = __float2half_rn(a - __half2float(ah));
        __half bl = __float2half_rn(b - __half2float(bh));
        hp[p] = __halves2half2(ah, bh);
        lp[p] = __halves2half2(al, bl);
    }
}
__device__ __forceinline__ uint32_t h2u(__half a, __half b){
    __half2 v = __halves2half2(a, b);
    return *reinterpret_cast<uint32_t*>(&v);
}

__global__ __launch_bounds__(CTA, 2)
void mlp_jvp_fp16(const float* __restrict__ x,
                  const float* __restrict__ emb,
                  const float* __restrict__ W1,
                  const float* __restrict__ b1,
                  const float* __restrict__ W2,
                  const float* __restrict__ b2,
                  const float* __restrict__ W3,
                  const float* __restrict__ b3,
                  float* __restrict__ out)
{
    extern __shared__ char smc[];
    const int tid = threadIdx.x;
    const int z   = blockIdx.y;

    /* ---- stage: E rows (own row), B1 = W1^T, W2t = W2^T, misc ---- */
    {
        const int n   = blockIdx.x * CTA + tid;
        const int bb  = n / LEN;
        const int tt  = n - bb * LEN;
        const int src = bb * 512 + tt + 2;           /* LL=512, LAGS=2 */
        const float4* e4 = reinterpret_cast<const float4*>(emb + (size_t)src * 32);
        float v[48];
        #pragma unroll
        for (int q = 0; q < 8; q++){
            float4 f = __ldg(e4 + q);
            v[4*q] = f.x; v[4*q+1] = f.y; v[4*q+2] = f.z; v[4*q+3] = f.w;
        }
        v[32] = x[src * ZDIM + z];
        #pragma unroll
        for (int q = 33; q < 48; q++) v[q] = 0.f;
        #pragma unroll
        for (int grp = 0; grp < 6; grp++){
            uint4 hi, lo; pack8(v + 8*grp, hi, lo);
            *reinterpret_cast<uint4*>(smc + R_EH + tid*SE1 + grp*16) = hi;
            *reinterpret_cast<uint4*>(smc + R_EL + tid*SE1 + grp*16) = lo;
        }
    }
    if (tid < 64){
        /* W2t[j][i] = W2[i][j] */
        const float* g2 = W2 + z*HDIM*HDIM;
        float v[64];
        #pragma unroll 8
        for (int i = 0; i < 64; i++) v[i] = g2[i*64 + tid];
        #pragma unroll
        for (int grp = 0; grp < 8; grp++){
            uint4 hi, lo; pack8(v + 8*grp, hi, lo);
            *reinterpret_cast<uint4*>(smc + R_W2H + tid*S2 + grp*16) = hi;
            *reinterpret_cast<uint4*>(smc + R_W2L + tid*S2 + grp*16) = lo;
        }
        const float* g1 = W1 + z*33*HDIM;
        reinterpret_cast<float*>(smc + M_B1)[tid] = b1[z*HDIM + tid];
        reinterpret_cast<float*>(smc + M_B2)[tid] = b2[z*HDIM + tid];
        float w3v = W3[z*HDIM + tid];
        reinterpret_cast<float*>(smc + M_W3)[tid]  = w3v;
        reinterpret_cast<float*>(smc + M_W3N)[tid] = NEG * w3v;
        float cw = g1[32*HDIM + tid];
        __half ch = __float2half_rn(cw);
        reinterpret_cast<__half*>(smc + M_CWH)[tid] = ch;
        reinterpret_cast<__half*>(smc + M_CWL)[tid] = __float2half_rn(cw - __half2float(ch));
        float cwn = NEG * cw;
        __half cnh = __float2half_rn(cwn);
        reinterpret_cast<__half*>(smc + M_CWNH)[tid] = cnh;
        reinterpret_cast<__half*>(smc + M_CWNL)[tid] = __float2half_rn(cwn - __half2float(cnh));
        if (tid == 0) *reinterpret_cast<float*>(smc + M_B3) = b3[z];
    } else {
        /* B1[h][e] = W1[e][h], cols 33..47 zero */
        const int h = tid - 64;
        const float* g1 = W1 + z*33*HDIM;
        float v[48];
        #pragma unroll 8
        for (int e = 0; e < 33; e++) v[e] = g1[e*64 + h];
        #pragma unroll
        for (int e = 33; e < 48; e++) v[e] = 0.f;
        #pragma unroll
        for (int grp = 0; grp < 6; grp++){
            uint4 hi, lo; pack8(v + 8*grp, hi, lo);
            *reinterpret_cast<uint4*>(smc + R_B1H + h*SE1 + grp*16) = hi;
            *reinterpret_cast<uint4*>(smc + R_B1L + h*SE1 + grp*16) = lo;
        }
    }
    __syncthreads();

    const int wid  = tid >> 5;
    const int lane = tid & 31;
    const int g    = lane >> 2;
    const int c    = lane & 3;
    const int rowbase = wid * 32;

    /* ---- layer 1: pre1 = [128x48] @ [48x64]^T, 3xFP16 split ---- */
    float C1[2][8][4];
    {
        const float* b1f = reinterpret_cast<const float*>(smc + M_B1);
        #pragma unroll
        for (int nf = 0; nf < 8; nf++){
            float bj0 = b1f[nf*8 + 2*c], bj1 = b1f[nf*8 + 2*c + 1];
            #pragma unroll
            for (int mf = 0; mf < 2; mf++){
                C1[mf][nf][0] = bj0; C1[mf][nf][1] = bj1;
                C1[mf][nf][2] = bj0; C1[mf][nf][3] = bj1;
            }
        }
        #pragma unroll
        for (int kb = 0; kb < 3; kb++){
            const int kby = (kb*16 + 2*c) * 2;       /* byte offset of col k0 */
            uint32_t Ah[2][4], Al[2][4];
            #pragma unroll
            for (int mf = 0; mf < 2; mf++){
                const char* eh = smc + R_EH + (rowbase + mf*16 + g)*SE1 + kby;
                const char* el = smc + R_EL + (rowbase + mf*16 + g)*SE1 + kby;
                Ah[mf][0] = *reinterpret_cast<const uint32_t*>(eh);
                Ah[mf][1] = *reinterpret_cast<const uint32_t*>(eh + 8*SE1);
                Ah[mf][2] = *reinterpret_cast<const uint32_t*>(eh + 16);
                Ah[mf][3] = *reinterpret_cast<const uint32_t*>(eh + 8*SE1 + 16);
                Al[mf][0] = *reinterpret_cast<const uint32_t*>(el);
                Al[mf][1] = *reinterpret_cast<const uint32_t*>(el + 8*SE1);
                Al[mf][2] = *reinterpret_cast<const uint32_t*>(el + 16);
                Al[mf][3] = *reinterpret_cast<const uint32_t*>(el + 8*SE1 + 16);
            }
            #pragma unroll
            for (int nf = 0; nf < 8; nf++){
                const char* bh = smc + R_B1H + (nf*8 + g)*SE1 + kby;
                const char* bl = smc + R_B1L + (nf*8 + g)*SE1 + kby;
                uint32_t bh0 = *reinterpret_cast<const uint32_t*>(bh);
                uint32_t bh1 = *reinterpret_cast<const uint32_t*>(bh + 16);
                uint32_t bl0 = *reinterpret_cast<const uint32_t*>(bl);
                uint32_t bl1 = *reinterpret_cast<const uint32_t*>(bl + 16);
                #pragma unroll
                for (int mf = 0; mf < 2; mf++){
                    mma16(C1[mf][nf], Ah[mf], bh0, bh1);
                    mma16(C1[mf][nf], Al[mf], bh0, bh1);
                    mma16(C1[mf][nf], Ah[mf], bl0, bl1);
                }
            }
        }
    }
    __syncthreads();   /* all warps done reading E/B1 before overwrite */

    /* ---- epilogue 1: leaky -> h tiles + tangent tiles (fp16 hi/lo) ---- */
    {
        const __half* cwh  = reinterpret_cast<const __half*>(smc + M_CWH);
        const __half* cwl  = reinterpret_cast<const __half*>(smc + M_CWL);
        const __half* cwnh = reinterpret_cast<const __half*>(smc + M_CWNH);
        const __half* cwnl = reinterpret_cast<const __half*>(smc + M_CWNL);
        #pragma unroll
        for (int mf = 0; mf < 2; mf++){
            #pragma unroll
            for (int nf = 0; nf < 8; nf++){
                const int j0 = nf*8 + 2*c;
                #pragma unroll
                for (int half_row = 0; half_row < 2; half_row++){
                    const int r = rowbase + mf*16 + g + half_row*8;
                    float p0 = C1[mf][nf][2*half_row + 0];
                    float p1 = C1[mf][nf][2*half_row + 1];
                    float h0 = leaky(p0), h1 = leaky(p1);
                    __half hh0 = __float2half_rn(h0);
                    __half hh1 = __float2half_rn(h1);
                    __half hl0 = __float2half_rn(h0 - __half2float(hh0));
                    __half hl1 = __float2half_rn(h1 - __half2float(hh1));
                    bool s0 = (p0 >= 0.f), s1 = (p1 >= 0.f);
                    uint32_t th = h2u(s0 ? cwh[j0] : cwnh[j0], s1 ? cwh[j0+1] : cwnh[j0+1]);
                    uint32_t tl = h2u(s0 ? cwl[j0] : cwnl[j0], s1 ? cwl[j0+1] : cwnl[j0+1]);
                    char* base = smc + r*S2 + j0*2;
                    *reinterpret_cast<uint32_t*>(base + R_A2H) = h2u(hh0, hh1);
                    *reinterpret_cast<uint32_t*>(base + R_A2L) = h2u(hl0, hl1);
                    *reinterpret_cast<uint32_t*>(base + R_TH)  = th;
                    *reinterpret_cast<uint32_t*>(base + R_TL)  = tl;
                }
            }
        }
    }
    __syncthreads();

    /* ---- layer 2 fused fwd+tangent, K=64, 3xFP16 each ---- */
    float Cf[2][8][4], Ct[2][8][4];
    {
        const float* b2f = reinterpret_cast<const float*>(smc + M_B2);
        #pragma unroll
        for (int nf = 0; nf < 8; nf++){
            float bj0 = b2f[nf*8 + 2*c], bj1 = b2f[nf*8 + 2*c + 1];
            #pragma unroll
            for (int mf = 0; mf < 2; mf++){
                Cf[mf][nf][0] = bj0; Cf[mf][nf][1] = bj1;
                Cf[mf][nf][2] = bj0; Cf[mf][nf][3] = bj1;
                Ct[mf][nf][0] = 0.f; Ct[mf][nf][1] = 0.f;
                Ct[mf][nf][2] = 0.f; Ct[mf][nf][3] = 0.f;
            }
        }
        #pragma unroll
        for (int kb = 0; kb < 4; kb++){
            const int kby = (kb*16 + 2*c) * 2;
            uint32_t Ah[2][4], Al[2][4], Th[2][4], Tl[2][4];
            #pragma unroll
            for (int mf = 0; mf < 2; mf++){
                const char* base = smc + (rowbase + mf*16 + g)*S2 + kby;
                Ah[mf][0] = *reinterpret_cast<const uint32_t*>(base + R_A2H);
                Ah[mf][1] = *reinterpret_cast<const uint32_t*>(base + R_A2H + 8*S2);
                Ah[mf][2] = *reinterpret_cast<const uint32_t*>(base + R_A2H + 16);
                Ah[mf][3] = *reinterpret_cast<const uint32_t*>(base + R_A2H + 8*S2 + 16);
                Al[mf][0] = *reinterpret_cast<const uint32_t*>(base + R_A2L);
                Al[mf][1] = *reinterpret_cast<const uint32_t*>(base + R_A2L + 8*S2);
                Al[mf][2] = *reinterpret_cast<const uint32_t*>(base + R_A2L + 16);
                Al[mf][3] = *reinterpret_cast<const uint32_t*>(base + R_A2L + 8*S2 + 16);
                Th[mf][0] = *reinterpret_cast<const uint32_t*>(base + R_TH);
                Th[mf][1] = *reinterpret_cast<const uint32_t*>(base + R_TH + 8*S2);
                Th[mf][2] = *reinterpret_cast<const uint32_t*>(base + R_TH + 16);
                Th[mf][3] = *reinterpret_cast<const uint32_t*>(base + R_TH + 8*S2 + 16);
                Tl[mf][0] = *reinterpret_cast<const uint32_t*>(base + R_TL);
                Tl[mf][1] = *reinterpret_cast<const uint32_t*>(base + R_TL + 8*S2);
                Tl[mf][2] = *reinterpret_cast<const uint32_t*>(base + R_TL + 16);
                Tl[mf][3] = *reinterpret_cast<const uint32_t*>(base + R_TL + 8*S2 + 16);
            }
            #pragma unroll
            for (int nf = 0; nf < 8; nf++){
                const char* wb = smc + (nf*8 + g)*S2 + kby;
                uint32_t bh0 = *reinterpret_cast<const uint32_t*>(wb + R_W2H);
                uint32_t bh1 = *reinterpret_cast<const uint32_t*>(wb + R_W2H + 16);
                uint32_t bl0 = *reinterpret_cast<const uint32_t*>(wb + R_W2L);
                uint32_t bl1 = *reinterpret_cast<const uint32_t*>(wb + R_W2L + 16);
                #pragma unroll
                for (int mf = 0; mf < 2; mf++){
                    mma16(Cf[mf][nf], Ah[mf], bh0, bh1);   /* B loaded once, feeds 6 mma */
                    mma16(Cf[mf][nf], Al[mf], bh0, bh1);
                    mma16(Cf[mf][nf], Ah[mf], bl0, bl1);
                    mma16(Ct[mf][nf], Th[mf], bh0, bh1);
                    mma16(Ct[mf][nf], Tl[mf], bh0, bh1);
                    mma16(Ct[mf][nf], Th[mf], bl0, bl1);
                }
            }
        }
    }

    /* ---- fused epilogue: leaky(pre2), layer-3 dots for fwd + tangent ---- */
    const float* w3f = reinterpret_cast<const float*>(smc + M_W3);
    const float* w3n = reinterpret_cast<const float*>(smc + M_W3N);
    float opart[4] = {0.f, 0.f, 0.f, 0.f};
    float dpart[4] = {0.f, 0.f, 0.f, 0.f};
    #pragma unroll
    for (int mf = 0; mf < 2; mf++)
    #pragma unroll
    for (int nf = 0; nf < 8; nf++)
    #pragma unroll
    for (int e = 0; e < 4; e++){
        float v = Cf[mf][nf][e];
        float t = Ct[mf][nf][e];
        int rs = mf*2 + (e>>1);
        int j  = nf*8 + 2*c + (e&1);
        bool s = (v >= 0.f);
        float h2 = s ? v : NEG * v;
        opart[rs] = fmaf(h2, w3f[j], opart[rs]);
        dpart[rs] = fmaf(s ? w3f[j] : w3n[j], t, dpart[rs]);
    }

    /* quad reduction and writeback */
    const float b3v = *reinterpret_cast<const float*>(smc + M_B3);
    #pragma unroll
    for (int rs = 0; rs < 4; rs++){
        float v = opart[rs];
        v += __shfl_xor_sync(0xffffffffu, v, 1);
        v += __shfl_xor_sync(0xffffffffu, v, 2);
        float d = dpart[rs];
        d += __shfl_xor_sync(0xffffffffu, d, 1);
        d += __shfl_xor_sync(0xffffffffu, d, 2);
        if (c == 0){
            int row  = rowbase + (rs>>1)*16 + (rs&1)*8 + g;
            int nrow = blockIdx.x * CTA + row;
            out[(size_t)nrow * ZDIM + z] = v + b3v;
            g_dlog[z*NTOT + nrow] = __logf(fabsf(d));
        }
    }
}

__global__ void logdet_reduce4(float* __restrict__ out){
    int t = blockIdx.x * blockDim.x + threadIdx.x;
    if (t >= NTOT/4) return;
    int base = t * 4;
    float4 s = make_float4(0.f, 0.f, 0.f, 0.f);
    #pragma unroll
    for (int zz = 0; zz < ZDIM; zz++){
        float4 v = *reinterpret_cast<const float4*>(&g_dlog[zz*NTOT + base]);
        s.x += v.x; s.y += v.y; s.z += v.z; s.w += v.w;
    }
    *reinterpret_cast<float4*>(&out[LOG_OFF + base]) = s;
}

extern "C" void kernel_launch(void* const* d_in, const int* in_sizes, int n_in,
                              void* d_out, int out_size){
    const float* x    = (const float*)d_in[0];
    const float* embv = (const float*)d_in[1];
    const float* W1   = (const float*)d_in[2];
    const float* b1   = (const float*)d_in[3];
    const float* W2   = (const float*)d_in[4];
    const float* b2   = (const float*)d_in[5];
    const float* W3   = (const float*)d_in[6];
    const float* b3   = (const float*)d_in[7];
    float* out = (float*)d_out;

    cudaFuncSetAttribute(mlp_jvp_fp16, cudaFuncAttributeMaxDynamicSharedMemorySize, SMEM_BYTES);
    dim3 grid(NTOT / CTA, ZDIM);
    mlp_jvp_fp16<<<grid, CTA, SMEM_BYTES>>>(x, embv, W1, b1, W2, b2, W3, b3, out);
    logdet_reduce4<<<(NTOT/4 + 255)/256, 256>>>(out);
}

// round 13
// speedup vs baseline: 1.9449x; 1.1101x over previous
#include <cuda_runtime.h>
#include <cuda_fp16.h>
#include <cstdint>

#define ZDIM 8
#define HDIM 64
#define NEG 0.01f
#define LEN 510
#define NTOT 32640            /* 64 * 510 = 255 * 128 */
#define LOG_OFF (NTOT*ZDIM)
#define CTA 128

#define S1 80                 /* phase-1 tile row stride, bytes (16B-aligned, conflict-free) */
#define S2 144                /* phase-2 tile row stride, bytes */

/* ---- smem byte offsets ---- */
/* phase-1 (dies after L1 mma; aliases phase-2 A/mask region) */
#define R_EH   0              /* E hi [128][32]h rows 64B @ stride 80 = 10240 */
#define R_EL   10240
#define R_B1H  20480          /* W1^T hi [64][32]h = 5120 */
#define R_B1L  25600
/* phase-2 (written in epilogue 1) */
#define R_A2H  0              /* h hi [128][72]h = 18432 */
#define R_A2L  18432
#define R_MSK  36864          /* mask {1.0, 0.01} fp16 */
/* persistent (staged up front) */
#define R_W2H  55296          /* W2^T hi [64][72]h = 9216 */
#define R_W2L  64512
#define R_WCH  73728          /* W2c^T = (cw*W2)^T hi */
#define R_WCL  82944
#define MISC   92160
#define M_B1   (MISC+0)       /* float[64] */
#define M_B2   (MISC+256)
#define M_W3   (MISC+512)
#define M_W3N  (MISC+768)
#define M_CW   (MISC+1024)    /* float[64] cw (for exact xt*cw epilogue) */
#define M_XT   (MISC+1280)    /* float[128] xt per row */
#define M_B3   (MISC+1792)
#define SMEM_BYTES (MISC+2048)   /* 94208 B -> 2 CTAs/SM */

__device__ float g_dlog[ZDIM * NTOT];

__device__ __forceinline__ void mma16(float* c, const uint32_t* a, uint32_t b0, uint32_t b1){
    asm volatile("mma.sync.aligned.m16n8k16.row.col.f32.f16.f16.f32 "
                 "{%0,%1,%2,%3}, {%4,%5,%6,%7}, {%8,%9}, {%0,%1,%2,%3};"
                 : "+f"(c[0]), "+f"(c[1]), "+f"(c[2]), "+f"(c[3])
                 : "r"(a[0]), "r"(a[1]), "r"(a[2]), "r"(a[3]), "r"(b0), "r"(b1));
}
__device__ __forceinline__ float leaky(float p){
    return fmaxf(p, 0.f) + NEG * fminf(p, 0.f);
}
__device__ __forceinline__ void pack8(const float* v, uint4& hi, uint4& lo){
    __half2* hp = reinterpret_cast<__half2*>(&hi);
    __half2* lp = reinterpret_cast<__half2*>(&lo);
    #pragma unroll
    for (int p = 0; p < 4; p++){
        float a = v[2*p], b = v[2*p+1];
        __half ah = __float2half_rn(a), bh = __float2half_rn(b);
        __half al = __float2half_rn(a - __half2float(ah));
        __half bl = __float2half_rn(b - __half2float(bh));
        hp[p] = __halves2half2(ah, bh);
        lp[p] = __halves2half2(al, bl);
    }
}
__device__ __forceinline__ uint32_t h2u(__half a, __half b){
    __half2 v = __halves2half2(a, b);
    return *reinterpret_cast<uint32_t*>(&v);
}

__global__ __launch_bounds__(CTA, 2)
void mlp_jvp_fp16(const float* __restrict__ x,
                  const float* __restrict__ emb,
                  const float* __restrict__ W1,
                  const float* __restrict__ b1,
                  const float* __restrict__ W2,
                  const float* __restrict__ b2,
                  const float* __restrict__ W3,
                  const float* __restrict__ b3,
                  float* __restrict__ out)
{
    extern __shared__ char smc[];
    const int tid = threadIdx.x;
    const int z   = blockIdx.y;

    /* ---- stage: E rows (own row) + xt, B1=W1^T, W2^T + W2c^T, misc ---- */
    {
        const int n   = blockIdx.x * CTA + tid;
        const int bb  = n / LEN;
        const int tt  = n - bb * LEN;
        const int src = bb * 512 + tt + 2;           /* LL=512, LAGS=2 */
        const float4* e4 = reinterpret_cast<const float4*>(emb + (size_t)src * 32);
        float v[32];
        #pragma unroll
        for (int q = 0; q < 8; q++){
            float4 f = __ldg(e4 + q);
            v[4*q] = f.x; v[4*q+1] = f.y; v[4*q+2] = f.z; v[4*q+3] = f.w;
        }
        #pragma unroll
        for (int grp = 0; grp < 4; grp++){
            uint4 hi, lo; pack8(v + 8*grp, hi, lo);
            *reinterpret_cast<uint4*>(smc + R_EH + tid*S1 + grp*16) = hi;
            *reinterpret_cast<uint4*>(smc + R_EL + tid*S1 + grp*16) = lo;
        }
        reinterpret_cast<float*>(smc + M_XT)[tid] = x[src * ZDIM + z];
    }
    if (tid < 64){
        /* W2t[j][i] = W2[i][j]; W2c[j][i] = cw_i * W2[i][j] */
        const float* g2 = W2 + z*HDIM*HDIM;
        const float* g1 = W1 + z*33*HDIM;
        const float* cwg = g1 + 32*HDIM;
        float v[64], vc[64];
        #pragma unroll 8
        for (int i = 0; i < 64; i++){
            float w = g2[i*64 + tid];
            v[i]  = w;
            vc[i] = __ldg(cwg + i) * w;              /* uniform-address cw broadcast */
        }
        #pragma unroll
        for (int grp = 0; grp < 8; grp++){
            uint4 hi, lo; pack8(v + 8*grp, hi, lo);
            *reinterpret_cast<uint4*>(smc + R_W2H + tid*S2 + grp*16) = hi;
            *reinterpret_cast<uint4*>(smc + R_W2L + tid*S2 + grp*16) = lo;
            pack8(vc + 8*grp, hi, lo);
            *reinterpret_cast<uint4*>(smc + R_WCH + tid*S2 + grp*16) = hi;
            *reinterpret_cast<uint4*>(smc + R_WCL + tid*S2 + grp*16) = lo;
        }
        reinterpret_cast<float*>(smc + M_B1)[tid] = b1[z*HDIM + tid];
        reinterpret_cast<float*>(smc + M_B2)[tid] = b2[z*HDIM + tid];
        float w3v = W3[z*HDIM + tid];
        reinterpret_cast<float*>(smc + M_W3)[tid]  = w3v;
        reinterpret_cast<float*>(smc + M_W3N)[tid] = NEG * w3v;
        reinterpret_cast<float*>(smc + M_CW)[tid]  = cwg[tid];
        if (tid == 0) *reinterpret_cast<float*>(smc + M_B3) = b3[z];
    } else {
        /* B1[h][e] = W1[e][h], 32 K-cols */
        const int h = tid - 64;
        const float* g1 = W1 + z*33*HDIM;
        float v[32];
        #pragma unroll 8
        for (int e = 0; e < 32; e++) v[e] = g1[e*64 + h];
        #pragma unroll
        for (int grp = 0; grp < 4; grp++){
            uint4 hi, lo; pack8(v + 8*grp, hi, lo);
            *reinterpret_cast<uint4*>(smc + R_B1H + h*S1 + grp*16) = hi;
            *reinterpret_cast<uint4*>(smc + R_B1L + h*S1 + grp*16) = lo;
        }
    }
    __syncthreads();

    const int wid  = tid >> 5;
    const int lane = tid & 31;
    const int g    = lane >> 2;
    const int c    = lane & 3;
    const int rowbase = wid * 32;

    /* ---- layer 1: pre1 = [128x32] @ [32x64]^T, 3xFP16 split, 2 K-blocks ---- */
    float C1[2][8][4];
    {
        const float* b1f = reinterpret_cast<const float*>(smc + M_B1);
        #pragma unroll
        for (int nf = 0; nf < 8; nf++){
            float bj0 = b1f[nf*8 + 2*c], bj1 = b1f[nf*8 + 2*c + 1];
            #pragma unroll
            for (int mf = 0; mf < 2; mf++){
                C1[mf][nf][0] = bj0; C1[mf][nf][1] = bj1;
                C1[mf][nf][2] = bj0; C1[mf][nf][3] = bj1;
            }
        }
        #pragma unroll
        for (int kb = 0; kb < 2; kb++){
            const int kby = kb*32 + 4*c;
            uint32_t Ah[2][4], Al[2][4];
            #pragma unroll
            for (int mf = 0; mf < 2; mf++){
                const char* eh = smc + R_EH + (rowbase + mf*16 + g)*S1 + kby;
                const char* el = smc + R_EL + (rowbase + mf*16 + g)*S1 + kby;
                Ah[mf][0] = *reinterpret_cast<const uint32_t*>(eh);
                Ah[mf][1] = *reinterpret_cast<const uint32_t*>(eh + 8*S1);
                Ah[mf][2] = *reinterpret_cast<const uint32_t*>(eh + 16);
                Ah[mf][3] = *reinterpret_cast<const uint32_t*>(eh + 8*S1 + 16);
                Al[mf][0] = *reinterpret_cast<const uint32_t*>(el);
                Al[mf][1] = *reinterpret_cast<const uint32_t*>(el + 8*S1);
                Al[mf][2] = *reinterpret_cast<const uint32_t*>(el + 16);
                Al[mf][3] = *reinterpret_cast<const uint32_t*>(el + 8*S1 + 16);
            }
            #pragma unroll
            for (int nf = 0; nf < 8; nf++){
                const char* bh = smc + R_B1H + (nf*8 + g)*S1 + kby;
                const char* bl = smc + R_B1L + (nf*8 + g)*S1 + kby;
                uint32_t bh0 = *reinterpret_cast<const uint32_t*>(bh);
                uint32_t bh1 = *reinterpret_cast<const uint32_t*>(bh + 16);
                uint32_t bl0 = *reinterpret_cast<const uint32_t*>(bl);
                uint32_t bl1 = *reinterpret_cast<const uint32_t*>(bl + 16);
                #pragma unroll
                for (int mf = 0; mf < 2; mf++){
                    mma16(C1[mf][nf], Ah[mf], bh0, bh1);
                    mma16(C1[mf][nf], Al[mf], bh0, bh1);
                    mma16(C1[mf][nf], Ah[mf], bl0, bl1);
                }
            }
        }
    }
    __syncthreads();   /* all warps done reading E/B1 before overwrite */

    /* ---- epilogue 1: pre1 += xt*cw (exact); leaky -> h hi/lo + mask tiles ---- */
    {
        const float* cwf = reinterpret_cast<const float*>(smc + M_CW);
        const float* xtf = reinterpret_cast<const float*>(smc + M_XT);
        const __half one  = __float2half_rn(1.0f);
        const __half hneg = __float2half_rn(NEG);
        #pragma unroll
        for (int mf = 0; mf < 2; mf++){
            #pragma unroll
            for (int hr = 0; hr < 2; hr++){
                const int r  = rowbase + mf*16 + g + hr*8;
                const float xr = xtf[r];
                #pragma unroll
                for (int nf = 0; nf < 8; nf++){
                    const int j0 = nf*8 + 2*c;
                    float p0 = fmaf(xr, cwf[j0],   C1[mf][nf][2*hr + 0]);
                    float p1 = fmaf(xr, cwf[j0+1], C1[mf][nf][2*hr + 1]);
                    float h0 = leaky(p0), h1 = leaky(p1);
                    __half hh0 = __float2half_rn(h0);
                    __half hh1 = __float2half_rn(h1);
                    __half hl0 = __float2half_rn(h0 - __half2float(hh0));
                    __half hl1 = __float2half_rn(h1 - __half2float(hh1));
                    bool s0 = (p0 >= 0.f), s1 = (p1 >= 0.f);
                    char* base = smc + r*S2 + j0*2;
                    *reinterpret_cast<uint32_t*>(base + R_A2H) = h2u(hh0, hh1);
                    *reinterpret_cast<uint32_t*>(base + R_A2L) = h2u(hl0, hl1);
                    *reinterpret_cast<uint32_t*>(base + R_MSK) = h2u(s0 ? one : hneg, s1 ? one : hneg);
                }
            }
        }
    }
    __syncthreads();

    /* ---- layer 2: fwd (3-term) + tangent (mask @ W2c, 2-term), K=64 ---- */
    float Cf[2][8][4], Ct[2][8][4];
    {
        const float* b2f = reinterpret_cast<const float*>(smc + M_B2);
        #pragma unroll
        for (int nf = 0; nf < 8; nf++){
            float bj0 = b2f[nf*8 + 2*c], bj1 = b2f[nf*8 + 2*c + 1];
            #pragma unroll
            for (int mf = 0; mf < 2; mf++){
                Cf[mf][nf][0] = bj0; Cf[mf][nf][1] = bj1;
                Cf[mf][nf][2] = bj0; Cf[mf][nf][3] = bj1;
                Ct[mf][nf][0] = 0.f; Ct[mf][nf][1] = 0.f;
                Ct[mf][nf][2] = 0.f; Ct[mf][nf][3] = 0.f;
            }
        }
        #pragma unroll
        for (int kb = 0; kb < 4; kb++){
            const int kby = kb*32 + 4*c;
            uint32_t Ah[2][4], Al[2][4], Tm[2][4];
            #pragma unroll
            for (int mf = 0; mf < 2; mf++){
                const char* base = smc + (rowbase + mf*16 + g)*S2 + kby;
                Ah[mf][0] = *reinterpret_cast<const uint32_t*>(base + R_A2H);
                Ah[mf][1] = *reinterpret_cast<const uint32_t*>(base + R_A2H + 8*S2);
                Ah[mf][2] = *reinterpret_cast<const uint32_t*>(base + R_A2H + 16);
                Ah[mf][3] = *reinterpret_cast<const uint32_t*>(base + R_A2H + 8*S2 + 16);
                Al[mf][0] = *reinterpret_cast<const uint32_t*>(base + R_A2L);
                Al[mf][1] = *reinterpret_cast<const uint32_t*>(base + R_A2L + 8*S2);
                Al[mf][2] = *reinterpret_cast<const uint32_t*>(base + R_A2L + 16);
                Al[mf][3] = *reinterpret_cast<const uint32_t*>(base + R_A2L + 8*S2 + 16);
                Tm[mf][0] = *reinterpret_cast<const uint32_t*>(base + R_MSK);
                Tm[mf][1] = *reinterpret_cast<const uint32_t*>(base + R_MSK + 8*S2);
                Tm[mf][2] = *reinterpret_cast<const uint32_t*>(base + R_MSK + 16);
                Tm[mf][3] = *reinterpret_cast<const uint32_t*>(base + R_MSK + 8*S2 + 16);
            }
            #pragma unroll
            for (int nf = 0; nf < 8; nf++){
                const char* wb = smc + (nf*8 + g)*S2 + kby;
                uint32_t bh0 = *reinterpret_cast<const uint32_t*>(wb + R_W2H);
                uint32_t bh1 = *reinterpret_cast<const uint32_t*>(wb + R_W2H + 16);
                uint32_t bl0 = *reinterpret_cast<const uint32_t*>(wb + R_W2L);
                uint32_t bl1 = *reinterpret_cast<const uint32_t*>(wb + R_W2L + 16);
                uint32_t ch0 = *reinterpret_cast<const uint32_t*>(wb + R_WCH);
                uint32_t ch1 = *reinterpret_cast<const uint32_t*>(wb + R_WCH + 16);
                uint32_t cl0 = *reinterpret_cast<const uint32_t*>(wb + R_WCL);
                uint32_t cl1 = *reinterpret_cast<const uint32_t*>(wb + R_WCL + 16);
                #pragma unroll
                for (int mf = 0; mf < 2; mf++){
                    mma16(Cf[mf][nf], Ah[mf], bh0, bh1);
                    mma16(Cf[mf][nf], Al[mf], bh0, bh1);
                    mma16(Cf[mf][nf], Ah[mf], bl0, bl1);
                    mma16(Ct[mf][nf], Tm[mf], ch0, ch1);
                    mma16(Ct[mf][nf], Tm[mf], cl0, cl1);
                }
            }
        }
    }

    /* ---- fused epilogue: leaky(pre2), layer-3 dots for fwd + tangent ---- */
    const float* w3f = reinterpret_cast<const float*>(smc + M_W3);
    const float* w3n = reinterpret_cast<const float*>(smc + M_W3N);
    float opart[4] = {0.f, 0.f, 0.f, 0.f};
    float dpart[4] = {0.f, 0.f, 0.f, 0.f};
    #pragma unroll
    for (int mf = 0; mf < 2; mf++)
    #pragma unroll
    for (int nf = 0; nf < 8; nf++)
    #pragma unroll
    for (int e = 0; e < 4; e++){
        float v = Cf[mf][nf][e];
        float t = Ct[mf][nf][e];
        int rs = mf*2 + (e>>1);
        int j  = nf*8 + 2*c + (e&1);
        bool s = (v >= 0.f);
        float h2 = s ? v : NEG * v;
        opart[rs] = fmaf(h2, w3f[j], opart[rs]);
        dpart[rs] = fmaf(s ? w3f[j] : w3n[j], t, dpart[rs]);
    }

    /* quad reduction and writeback */
    const float b3v = *reinterpret_cast<const float*>(smc + M_B3);
    #pragma unroll
    for (int rs = 0; rs < 4; rs++){
        float v = opart[rs];
        v += __shfl_xor_sync(0xffffffffu, v, 1);
        v += __shfl_xor_sync(0xffffffffu, v, 2);
        float d = dpart[rs];
        d += __shfl_xor_sync(0xffffffffu, d, 1);
        d += __shfl_xor_sync(0xffffffffu, d, 2);
        if (c == 0){
            int row  = rowbase + (rs>>1)*16 + (rs&1)*8 + g;
            int nrow = blockIdx.x * CTA + row;
            out[(size_t)nrow * ZDIM + z] = v + b3v;
            g_dlog[z*NTOT + nrow] = __logf(fabsf(d));
        }
    }
}

__global__ void logdet_reduce4(float* __restrict__ out){
    int t = blockIdx.x * blockDim.x + threadIdx.x;
    if (t >= NTOT/4) return;
    int base = t * 4;
    float4 s = make_float4(0.f, 0.f, 0.f, 0.f);
    #pragma unroll
    for (int zz = 0; zz < ZDIM; zz++){
        float4 v = *reinterpret_cast<const float4*>(&g_dlog[zz*NTOT + base]);
        s.x += v.x; s.y += v.y; s.z += v.z; s.w += v.w;
    }
    *reinterpret_cast<float4*>(&out[LOG_OFF + base]) = s;
}

extern "C" void kernel_launch(void* const* d_in, const int* in_sizes, int n_in,
                              void* d_out, int out_size){
    const float* x    = (const float*)d_in[0];
    const float* embv = (const float*)d_in[1];
    const float* W1   = (const float*)d_in[2];
    const float* b1   = (const float*)d_in[3];
    const float* W2   = (const float*)d_in[4];
    const float* b2   = (const float*)d_in[5];
    const float* W3   = (const float*)d_in[6];
    const float* b3   = (const float*)d_in[7];
    float* out = (float*)d_out;

    cudaFuncSetAttribute(mlp_jvp_fp16, cudaFuncAttributeMaxDynamicSharedMemorySize, SMEM_BYTES);
    dim3 grid(NTOT / CTA, ZDIM);
    mlp_jvp_fp16<<<grid, CTA, SMEM_BYTES>>>(x, embv, W1, b1, W2, b2, W3, b3, out);
    logdet_reduce4<<<(NTOT/4 + 255)/256, 256>>>(out);
}

// round 14
// speedup vs baseline: 1.9531x; 1.0042x over previous
#include <cuda_runtime.h>
#include <cuda_fp16.h>
#include <cstdint>

#define ZDIM 8
#define HDIM 64
#define NEG 0.01f
#define LEN 510
#define NTOT 32640            /* 64 * 510 = 255 * 128 */
#define LOG_OFF (NTOT*ZDIM)
#define CTA 128

#define S1 80                 /* phase-1 tile row stride, bytes */
#define S2 144                /* phase-2 tile row stride, bytes */

/* ---- smem byte offsets ---- */
#define R_EH   0              /* E hi [128] rows 64B @ stride 80 = 10240 */
#define R_EL   10240
#define R_B1H  20480          /* W1^T hi [64][32]h = 5120 */
#define R_B1L  25600
#define R_A2H  0              /* h hi [128][72]h = 18432 (aliases E after L1) */
#define R_A2L  18432
#define R_MSK  36864          /* mask {1,0} fp16 */
#define R_W2H  55296          /* W2^T hi [64][72]h = 9216 */
#define R_W2L  64512
#define R_WCH  73728          /* W2c^T = (cw*W2)^T hi */
#define R_WCL  82944
#define MISC   92160
#define M_B1   (MISC+0)
#define M_B2   (MISC+256)
#define M_W3   (MISC+512)
#define M_W3N  (MISC+768)
#define M_CW   (MISC+1024)
#define M_XT   (MISC+1280)    /* float[128] */
#define M_B3   (MISC+1792)
#define M_TCOL (MISC+2048)    /* float[64]: Tcol_j = sum_i cw_i*W2[i][j] */
#define SMEM_BYTES (MISC+2560)

__device__ float g_dlog[ZDIM * NTOT];

__device__ __forceinline__ uint32_t smem_u32(const void* p){
    uint32_t a;
    asm("{ .reg .u64 t; cvta.to.shared.u64 t, %1; cvt.u32.u64 %0, t; }" : "=r"(a) : "l"(p));
    return a;
}
__device__ __forceinline__ void ldsm4(uint32_t& r0, uint32_t& r1, uint32_t& r2, uint32_t& r3, uint32_t addr){
    asm volatile("ldmatrix.sync.aligned.m8n8.x4.shared.b16 {%0,%1,%2,%3}, [%4];"
                 : "=r"(r0), "=r"(r1), "=r"(r2), "=r"(r3) : "r"(addr));
}
__device__ __forceinline__ void mma16(float* c, const uint32_t* a, uint32_t b0, uint32_t b1){
    asm volatile("mma.sync.aligned.m16n8k16.row.col.f32.f16.f16.f32 "
                 "{%0,%1,%2,%3}, {%4,%5,%6,%7}, {%8,%9}, {%0,%1,%2,%3};"
                 : "+f"(c[0]), "+f"(c[1]), "+f"(c[2]), "+f"(c[3])
                 : "r"(a[0]), "r"(a[1]), "r"(a[2]), "r"(a[3]), "r"(b0), "r"(b1));
}
__device__ __forceinline__ float leaky(float p){
    return fmaxf(p, 0.f) + NEG * fminf(p, 0.f);
}
__device__ __forceinline__ void pack8(const float* v, uint4& hi, uint4& lo){
    __half2* hp = reinterpret_cast<__half2*>(&hi);
    __half2* lp = reinterpret_cast<__half2*>(&lo);
    #pragma unroll
    for (int p = 0; p < 4; p++){
        float a = v[2*p], b = v[2*p+1];
        __half ah = __float2half_rn(a), bh = __float2half_rn(b);
        __half al = __float2half_rn(a - __half2float(ah));
        __half bl = __float2half_rn(b - __half2float(bh));
        hp[p] = __halves2half2(ah, bh);
        lp[p] = __halves2half2(al, bl);
    }
}
__device__ __forceinline__ uint32_t h2u(__half a, __half b){
    __half2 v = __halves2half2(a, b);
    return *reinterpret_cast<uint32_t*>(&v);
}

__global__ __launch_bounds__(CTA, 2)
void mlp_jvp_fp16(const float* __restrict__ x,
                  const float* __restrict__ emb,
                  const float* __restrict__ W1,
                  const float* __restrict__ b1,
                  const float* __restrict__ W2,
                  const float* __restrict__ b2,
                  const float* __restrict__ W3,
                  const float* __restrict__ b3,
                  float* __restrict__ out)
{
    extern __shared__ char smc[];
    const uint32_t sb = smem_u32(smc);
    const int tid = threadIdx.x;
    const int z   = blockIdx.y;

    /* ---- stage: E rows + xt; B1=W1^T; W2^T, W2c^T, Tcol; misc ---- */
    {
        const int n   = blockIdx.x * CTA + tid;
        const int bb  = n / LEN;
        const int tt  = n - bb * LEN;
        const int src = bb * 512 + tt + 2;           /* LL=512, LAGS=2 */
        const float4* e4 = reinterpret_cast<const float4*>(emb + (size_t)src * 32);
        float v[32];
        #pragma unroll
        for (int q = 0; q < 8; q++){
            float4 f = __ldg(e4 + q);
            v[4*q] = f.x; v[4*q+1] = f.y; v[4*q+2] = f.z; v[4*q+3] = f.w;
        }
        #pragma unroll
        for (int grp = 0; grp < 4; grp++){
            uint4 hi, lo; pack8(v + 8*grp, hi, lo);
            *reinterpret_cast<uint4*>(smc + R_EH + tid*S1 + grp*16) = hi;
            *reinterpret_cast<uint4*>(smc + R_EL + tid*S1 + grp*16) = lo;
        }
        reinterpret_cast<float*>(smc + M_XT)[tid] = x[src * ZDIM + z];
    }
    if (tid < 64){
        const float* g2 = W2 + z*HDIM*HDIM;
        const float* g1 = W1 + z*33*HDIM;
        const float* cwg = g1 + 32*HDIM;
        float v[64], vc[64];
        float tsum = 0.f;
        #pragma unroll 8
        for (int i = 0; i < 64; i++){
            float w = g2[i*64 + tid];
            v[i]  = w;
            float c = __ldg(cwg + i) * w;
            vc[i] = c;
            tsum += c;                               /* Tcol_j exact fp32 */
        }
        #pragma unroll
        for (int grp = 0; grp < 8; grp++){
            uint4 hi, lo; pack8(v + 8*grp, hi, lo);
            *reinterpret_cast<uint4*>(smc + R_W2H + tid*S2 + grp*16) = hi;
            *reinterpret_cast<uint4*>(smc + R_W2L + tid*S2 + grp*16) = lo;
            pack8(vc + 8*grp, hi, lo);
            *reinterpret_cast<uint4*>(smc + R_WCH + tid*S2 + grp*16) = hi;
            *reinterpret_cast<uint4*>(smc + R_WCL + tid*S2 + grp*16) = lo;
        }
        reinterpret_cast<float*>(smc + M_TCOL)[tid] = tsum;
        reinterpret_cast<float*>(smc + M_B1)[tid] = b1[z*HDIM + tid];
        reinterpret_cast<float*>(smc + M_B2)[tid] = b2[z*HDIM + tid];
        float w3v = W3[z*HDIM + tid];
        reinterpret_cast<float*>(smc + M_W3)[tid]  = w3v;
        reinterpret_cast<float*>(smc + M_W3N)[tid] = NEG * w3v;
        reinterpret_cast<float*>(smc + M_CW)[tid]  = cwg[tid];
        if (tid == 0) *reinterpret_cast<float*>(smc + M_B3) = b3[z];
    } else {
        const int h = tid - 64;
        const float* g1 = W1 + z*33*HDIM;
        float v[32];
        #pragma unroll 8
        for (int e = 0; e < 32; e++) v[e] = g1[e*64 + h];
        #pragma unroll
        for (int grp = 0; grp < 4; grp++){
            uint4 hi, lo; pack8(v + 8*grp, hi, lo);
            *reinterpret_cast<uint4*>(smc + R_B1H + h*S1 + grp*16) = hi;
            *reinterpret_cast<uint4*>(smc + R_B1L + h*S1 + grp*16) = lo;
        }
    }
    __syncthreads();

    const int wid  = tid >> 5;
    const int lane = tid & 31;
    const int g    = lane >> 2;
    const int c    = lane & 3;
    const int rowbase = wid * 32;
    /* ldmatrix lane mapping: m = lane>>3 selects matrix, rr = lane&7 its row */
    const int lm   = lane >> 3;
    const int rr   = lane & 7;
    const int rowadd = (lm & 1) * 8;        /* A: m1/m3 -> rows +8 */
    const int coladd = (lm >> 1) * 16;      /* A: m2/m3 -> cols +8 (16B) */

    /* ---- layer 1: pre1 = [128x32] @ [32x64]^T, 3xFP16 split ---- */
    float C1[2][8][4];
    {
        const float* b1f = reinterpret_cast<const float*>(smc + M_B1);
        #pragma unroll
        for (int nf = 0; nf < 8; nf++){
            float bj0 = b1f[nf*8 + 2*c], bj1 = b1f[nf*8 + 2*c + 1];
            #pragma unroll
            for (int mf = 0; mf < 2; mf++){
                C1[mf][nf][0] = bj0; C1[mf][nf][1] = bj1;
                C1[mf][nf][2] = bj0; C1[mf][nf][3] = bj1;
            }
        }
        /* A addresses (E tiles): row = rowbase + mf*16 + rowadd + rr */
        uint32_t aEh = sb + R_EH + (uint32_t)(rowbase + rowadd + rr)*S1 + coladd;
        uint32_t aEl = aEh + (R_EL - R_EH);
        /* B pair address: m0/m1 = B1H cols 0/8; m2/m3 = B1L cols 0/8 */
        uint32_t aB1 = sb + R_B1H + (uint32_t)rr*S1 + (lm & 1)*16 + (lm >> 1)*(R_B1L - R_B1H);
        #pragma unroll
        for (int kb = 0; kb < 2; kb++){
            uint32_t Ah[2][4], Al[2][4];
            #pragma unroll
            for (int mf = 0; mf < 2; mf++){
                ldsm4(Ah[mf][0], Ah[mf][1], Ah[mf][2], Ah[mf][3], aEh + mf*16*S1 + kb*32);
                ldsm4(Al[mf][0], Al[mf][1], Al[mf][2], Al[mf][3], aEl + mf*16*S1 + kb*32);
            }
            #pragma unroll
            for (int nf = 0; nf < 8; nf++){
                uint32_t bh0, bh1, bl0, bl1;
                ldsm4(bh0, bh1, bl0, bl1, aB1 + nf*8*S1 + kb*32);
                #pragma unroll
                for (int mf = 0; mf < 2; mf++){
                    mma16(C1[mf][nf], Ah[mf], bh0, bh1);
                    mma16(C1[mf][nf], Al[mf], bh0, bh1);
                    mma16(C1[mf][nf], Ah[mf], bl0, bl1);
                }
            }
        }
    }
    __syncthreads();   /* E/B1 dead; safe to overwrite with h/mask tiles */

    /* ---- epilogue 1: pre1 += xt*cw (exact); h hi/lo + exact {1,0} mask ---- */
    {
        const float* cwf = reinterpret_cast<const float*>(smc + M_CW);
        const float* xtf = reinterpret_cast<const float*>(smc + M_XT);
        const __half one  = __float2half_rn(1.0f);
        const __half zero = __float2half_rn(0.0f);
        #pragma unroll
        for (int mf = 0; mf < 2; mf++){
            #pragma unroll
            for (int hr = 0; hr < 2; hr++){
                const int r  = rowbase + mf*16 + g + hr*8;
                const float xr = xtf[r];
                #pragma unroll
                for (int nf = 0; nf < 8; nf++){
                    const int j0 = nf*8 + 2*c;
                    float p0 = fmaf(xr, cwf[j0],   C1[mf][nf][2*hr + 0]);
                    float p1 = fmaf(xr, cwf[j0+1], C1[mf][nf][2*hr + 1]);
                    float h0 = leaky(p0), h1 = leaky(p1);
                    __half hh0 = __float2half_rn(h0);
                    __half hh1 = __float2half_rn(h1);
                    __half hl0 = __float2half_rn(h0 - __half2float(hh0));
                    __half hl1 = __float2half_rn(h1 - __half2float(hh1));
                    bool s0 = (p0 >= 0.f), s1 = (p1 >= 0.f);
                    char* base = smc + r*S2 + j0*2;
                    *reinterpret_cast<uint32_t*>(base + R_A2H) = h2u(hh0, hh1);
                    *reinterpret_cast<uint32_t*>(base + R_A2L) = h2u(hl0, hl1);
                    *reinterpret_cast<uint32_t*>(base + R_MSK) = h2u(s0 ? one : zero, s1 ? one : zero);
                }
            }
        }
    }
    __syncthreads();

    /* ---- layer 2: fwd (3-term) + tangent (exact mask @ W2c, 2-term) ---- */
    float Cf[2][8][4], Ct[2][8][4];
    {
        const float* b2f = reinterpret_cast<const float*>(smc + M_B2);
        #pragma unroll
        for (int nf = 0; nf < 8; nf++){
            float bj0 = b2f[nf*8 + 2*c], bj1 = b2f[nf*8 + 2*c + 1];
            #pragma unroll
            for (int mf = 0; mf < 2; mf++){
                Cf[mf][nf][0] = bj0; Cf[mf][nf][1] = bj1;
                Cf[mf][nf][2] = bj0; Cf[mf][nf][3] = bj1;
                Ct[mf][nf][0] = 0.f; Ct[mf][nf][1] = 0.f;
                Ct[mf][nf][2] = 0.f; Ct[mf][nf][3] = 0.f;
            }
        }
        uint32_t aAh = sb + R_A2H + (uint32_t)(rowbase + rowadd + rr)*S2 + coladd;
        uint32_t aAl = aAh + (R_A2L - R_A2H);
        uint32_t aTm = aAh + (R_MSK - R_A2H);
        uint32_t aW  = sb + R_W2H + (uint32_t)rr*S2 + (lm & 1)*16 + (lm >> 1)*(R_W2L - R_W2H);
        uint32_t aC  = sb + R_WCH + (uint32_t)rr*S2 + (lm & 1)*16 + (lm >> 1)*(R_WCL - R_WCH);
        #pragma unroll
        for (int kb = 0; kb < 4; kb++){
            uint32_t Ah[2][4], Al[2][4], Tm[2][4];
            #pragma unroll
            for (int mf = 0; mf < 2; mf++){
                ldsm4(Ah[mf][0], Ah[mf][1], Ah[mf][2], Ah[mf][3], aAh + mf*16*S2 + kb*32);
                ldsm4(Al[mf][0], Al[mf][1], Al[mf][2], Al[mf][3], aAl + mf*16*S2 + kb*32);
                ldsm4(Tm[mf][0], Tm[mf][1], Tm[mf][2], Tm[mf][3], aTm + mf*16*S2 + kb*32);
            }
            #pragma unroll
            for (int nf = 0; nf < 8; nf++){
                uint32_t bh0, bh1, bl0, bl1, ch0, ch1, cl0, cl1;
                ldsm4(bh0, bh1, bl0, bl1, aW + nf*8*S2 + kb*32);
                ldsm4(ch0, ch1, cl0, cl1, aC + nf*8*S2 + kb*32);
                #pragma unroll
                for (int mf = 0; mf < 2; mf++){
                    mma16(Cf[mf][nf], Ah[mf], bh0, bh1);
                    mma16(Cf[mf][nf], Al[mf], bh0, bh1);
                    mma16(Cf[mf][nf], Ah[mf], bl0, bl1);
                    mma16(Ct[mf][nf], Tm[mf], ch0, ch1);
                    mma16(Ct[mf][nf], Tm[mf], cl0, cl1);
                }
            }
        }
    }

    /* ---- fused epilogue: leaky(pre2); dpre2 = 0.99*P + 0.01*Tcol; W3 dots ---- */
    const float* w3f  = reinterpret_cast<const float*>(smc + M_W3);
    const float* w3n  = reinterpret_cast<const float*>(smc + M_W3N);
    const float* tcol = reinterpret_cast<const float*>(smc + M_TCOL);
    float opart[4] = {0.f, 0.f, 0.f, 0.f};
    float dpart[4] = {0.f, 0.f, 0.f, 0.f};
    #pragma unroll
    for (int mf = 0; mf < 2; mf++)
    #pragma unroll
    for (int nf = 0; nf < 8; nf++)
    #pragma unroll
    for (int e = 0; e < 4; e++){
        float v = Cf[mf][nf][e];
        float P = Ct[mf][nf][e];
        int rs = mf*2 + (e>>1);
        int j  = nf*8 + 2*c + (e&1);
        float t = fmaf(0.99f, P, 0.01f * tcol[j]);   /* exact-mask correction */
        bool s = (v >= 0.f);
        float h2 = s ? v : NEG * v;
        opart[rs] = fmaf(h2, w3f[j], opart[rs]);
        dpart[rs] = fmaf(s ? w3f[j] : w3n[j], t, dpart[rs]);
    }

    /* quad reduction and writeback */
    const float b3v = *reinterpret_cast<const float*>(smc + M_B3);
    #pragma unroll
    for (int rs = 0; rs < 4; rs++){
        float v = opart[rs];
        v += __shfl_xor_sync(0xffffffffu, v, 1);
        v += __shfl_xor_sync(0xffffffffu, v, 2);
        float d = dpart[rs];
        d += __shfl_xor_sync(0xffffffffu, d, 1);
        d += __shfl_xor_sync(0xffffffffu, d, 2);
        if (c == 0){
            int row  = rowbase + (rs>>1)*16 + (rs&1)*8 + g;
            int nrow = blockIdx.x * CTA + row;
            out[(size_t)nrow * ZDIM + z] = v + b3v;
            g_dlog[z*NTOT + nrow] = __logf(fabsf(d));
        }
    }
}

__global__ void logdet_reduce4(float* __restrict__ out){
    int t = blockIdx.x * blockDim.x + threadIdx.x;
    if (t >= NTOT/4) return;
    int base = t * 4;
    float4 s = make_float4(0.f, 0.f, 0.f, 0.f);
    #pragma unroll
    for (int zz = 0; zz < ZDIM; zz++){
        float4 v = *reinterpret_cast<const float4*>(&g_dlog[zz*NTOT + base]);
        s.x += v.x; s.y += v.y; s.z += v.z; s.w += v.w;
    }
    *reinterpret_cast<float4*>(&out[LOG_OFF + base]) = s;
}

extern "C" void kernel_launch(void* const* d_in, const int* in_sizes, int n_in,
                              void* d_out, int out_size){
    const float* x    = (const float*)d_in[0];
    const float* embv = (const float*)d_in[1];
    const float* W1   = (const float*)d_in[2];
    const float* b1   = (const float*)d_in[3];
    const float* W2   = (const float*)d_in[4];
    const float* b2   = (const float*)d_in[5];
    const float* W3   = (const float*)d_in[6];
    const float* b3   = (const float*)d_in[7];
    float* out = (float*)d_out;

    cudaFuncSetAttribute(mlp_jvp_fp16, cudaFuncAttributeMaxDynamicSharedMemorySize, SMEM_BYTES);
    dim3 grid(NTOT / CTA, ZDIM);
    mlp_jvp_fp16<<<grid, CTA, SMEM_BYTES>>>(x, embv, W1, b1, W2, b2, W3, b3, out);
    logdet_reduce4<<<(NTOT/4 + 255)/256, 256>>>(out);
}